// round 1
// baseline (speedup 1.0000x reference)
#include <cuda_runtime.h>
#include <math.h>

#define SLEN 4096
#define DIM  256
#define HID  512
#define H4   2048
#define NE   2000
#define NL   20
#define GCTA 32      // CTAs per direction
#define HPC  16      // h-indices per CTA (HID / GCTA)

// ---------------- device scratch (static: no runtime allocation) -------------
__device__ float g_xw[2][SLEN][H4];          // 64 MB: precomputed x@Wi^T + b
__device__ float g_hs[2][SLEN][HID];         // 16 MB: full hidden-state history
__device__ float g_scores[SLEN];
__device__ unsigned int g_prog[2][GCTA][32]; // progress counters, 128B padded

__device__ __forceinline__ float sigmoidf_(float x) {
    return 1.0f / (1.0f + __expf(-x));
}

// ---------------- kernel 1: xW GEMM with fused embedding gather --------------
// C[m][n] = sum_k emb[sent[m]][k] * Wi[n][k] + b[n];  M=4096, N=2048, K=256
__global__ void __launch_bounds__(256) xw_gemm_kernel(
    const int* __restrict__ sent, const float* __restrict__ emb,
    const float* __restrict__ Wi_f, const float* __restrict__ b_f,
    const float* __restrict__ Wi_b, const float* __restrict__ b_b)
{
    const int dir = blockIdx.z;
    const float* __restrict__ Wi   = dir ? Wi_b : Wi_f;
    const float* __restrict__ bias = dir ? b_b : b_f;
    const int n0 = blockIdx.x * 64;
    const int m0 = blockIdx.y * 64;

    __shared__ float As[16][64];
    __shared__ float Bs[16][64];
    __shared__ int   rows[64];

    const int tid = threadIdx.x;
    if (tid < 64) rows[tid] = sent[m0 + tid];
    __syncthreads();

    const int lm = tid >> 2;          // 0..63 (row within tile)
    const int lk = (tid & 3) * 4;     // 0,4,8,12 (k offset)
    const int ty = (tid >> 4) * 4;    // m micro-offset
    const int tx = (tid & 15) * 4;    // n micro-offset

    float acc[4][4];
    #pragma unroll
    for (int i = 0; i < 4; i++)
        #pragma unroll
        for (int j = 0; j < 4; j++) acc[i][j] = 0.0f;

    for (int k0 = 0; k0 < DIM; k0 += 16) {
        float4 a = *(const float4*)&emb[(long)rows[lm] * DIM + k0 + lk];
        float4 b = *(const float4*)&Wi[(long)(n0 + lm) * DIM + k0 + lk];
        __syncthreads();
        As[lk + 0][lm] = a.x; As[lk + 1][lm] = a.y;
        As[lk + 2][lm] = a.z; As[lk + 3][lm] = a.w;
        Bs[lk + 0][lm] = b.x; Bs[lk + 1][lm] = b.y;
        Bs[lk + 2][lm] = b.z; Bs[lk + 3][lm] = b.w;
        __syncthreads();
        #pragma unroll
        for (int kk = 0; kk < 16; kk++) {
            float4 a4 = *(const float4*)&As[kk][ty];
            float4 b4 = *(const float4*)&Bs[kk][tx];
            float av[4] = {a4.x, a4.y, a4.z, a4.w};
            float bv[4] = {b4.x, b4.y, b4.z, b4.w};
            #pragma unroll
            for (int i = 0; i < 4; i++)
                #pragma unroll
                for (int j = 0; j < 4; j++)
                    acc[i][j] = fmaf(av[i], bv[j], acc[i][j]);
        }
    }

    float4 bb = *(const float4*)&bias[n0 + tx];
    float bvv[4] = {bb.x, bb.y, bb.z, bb.w};
    #pragma unroll
    for (int i = 0; i < 4; i++) {
        float4 o;
        o.x = acc[i][0] + bvv[0];
        o.y = acc[i][1] + bvv[1];
        o.z = acc[i][2] + bvv[2];
        o.w = acc[i][3] + bvv[3];
        *(float4*)&g_xw[dir][m0 + ty + i][n0 + tx] = o;
    }
}

// ---------------- kernel 2: persistent BiLSTM with cross-SM flag sync --------
__global__ void __launch_bounds__(512, 1) lstm_kernel(
    const float* __restrict__ Wh_f, const float* __restrict__ Wh_b)
{
    const int dir  = (blockIdx.x >= GCTA) ? 1 : 0;
    const int g    = blockIdx.x & (GCTA - 1);
    const float* __restrict__ Wh = dir ? Wh_b : Wh_f;

    const int tid  = threadIdx.x;
    const int w    = tid >> 5;       // warp -> local h-index
    const int lane = tid & 31;
    const int hidx = g * HPC + w;    // global h-index 0..511
    const int k0   = lane * 16;      // k slice

    // recurrent weights for (hidx, 4 gates, k0..k0+15) -> registers
    float wi[16], wf[16], wg[16], wo[16];
    {
        const float4* pi = (const float4*)&Wh[(long)(0 * HID + hidx) * HID + k0];
        const float4* pf = (const float4*)&Wh[(long)(1 * HID + hidx) * HID + k0];
        const float4* pg = (const float4*)&Wh[(long)(2 * HID + hidx) * HID + k0];
        const float4* po = (const float4*)&Wh[(long)(3 * HID + hidx) * HID + k0];
        #pragma unroll
        for (int q = 0; q < 4; q++) {
            float4 v;
            v = pi[q]; wi[4*q] = v.x; wi[4*q+1] = v.y; wi[4*q+2] = v.z; wi[4*q+3] = v.w;
            v = pf[q]; wf[4*q] = v.x; wf[4*q+1] = v.y; wf[4*q+2] = v.z; wf[4*q+3] = v.w;
            v = pg[q]; wg[4*q] = v.x; wg[4*q+1] = v.y; wg[4*q+2] = v.z; wg[4*q+3] = v.w;
            v = po[q]; wo[4*q] = v.x; wo[4*q+1] = v.y; wo[4*q+2] = v.z; wo[4*q+3] = v.w;
        }
    }

    volatile unsigned int* myprog = &g_prog[dir][g][0];
    if (tid == 0) *myprog = 0u;

    float c = 0.0f;   // cell state (lane 0 of each warp owns it)
    float* hs = &g_hs[dir][0][0];
    const float* xw = &g_xw[dir][0][0];

    for (int s = 0; s < SLEN; s++) {
        const int tok = dir ? (SLEN - 1 - s) : s;

        // prefetch input projection (independent of h) before polling
        float xi = 0.f, xf = 0.f, xg = 0.f, xo = 0.f;
        if (lane == 0) {
            const float* xr = xw + (long)tok * H4 + hidx;
            xi = __ldcg(xr);
            xf = __ldcg(xr + HID);
            xg = __ldcg(xr + 2 * HID);
            xo = __ldcg(xr + 3 * HID);
        }

        float zi = 0.f, zf = 0.f, zg = 0.f, zo = 0.f;
        if (s > 0) {
            if (tid < GCTA) {
                volatile unsigned int* p = &g_prog[dir][tid][0];
                while (*p < (unsigned)s) { }
                __threadfence();   // acquire-side fence after observing flag
            }
            __syncthreads();

            const int ptok = dir ? (tok + 1) : (tok - 1);
            const float4* hp = (const float4*)(hs + (long)ptok * HID + k0);
            float4 h0 = __ldcg(hp + 0);
            float4 h1 = __ldcg(hp + 1);
            float4 h2 = __ldcg(hp + 2);
            float4 h3 = __ldcg(hp + 3);
            float hv[16] = {h0.x, h0.y, h0.z, h0.w, h1.x, h1.y, h1.z, h1.w,
                            h2.x, h2.y, h2.z, h2.w, h3.x, h3.y, h3.z, h3.w};
            #pragma unroll
            for (int j = 0; j < 16; j++) {
                zi = fmaf(wi[j], hv[j], zi);
                zf = fmaf(wf[j], hv[j], zf);
                zg = fmaf(wg[j], hv[j], zg);
                zo = fmaf(wo[j], hv[j], zo);
            }
        }

        // warp reduction over the 32 k-slices
        #pragma unroll
        for (int off = 16; off; off >>= 1) {
            zi += __shfl_down_sync(0xffffffffu, zi, off);
            zf += __shfl_down_sync(0xffffffffu, zf, off);
            zg += __shfl_down_sync(0xffffffffu, zg, off);
            zo += __shfl_down_sync(0xffffffffu, zo, off);
        }

        if (lane == 0) {
            zi += xi; zf += xf; zg += xg; zo += xo;
            float i_ = sigmoidf_(zi);
            float f_ = sigmoidf_(zf);
            float o_ = sigmoidf_(zo);
            float gg = tanhf(zg);
            c = fmaf(f_, c, i_ * gg);
            float h = o_ * tanhf(c);
            __stcg(hs + (long)tok * HID + hidx, h);
        }
        __syncthreads();
        if (tid == 0) { __threadfence(); *myprog = (unsigned)(s + 1); }
    }
}

// ---------------- kernel 3: attention scores ---------------------------------
__global__ void __launch_bounds__(256) scores_kernel(
    const float* __restrict__ attn_w, const float* __restrict__ attn_b)
{
    const int t = blockIdx.x;
    const int tid = threadIdx.x;
    float acc = 0.0f;
    const float* hf = &g_hs[0][t][0];
    const float* hb = &g_hs[1][t][0];
    for (int j = tid; j < HID; j += 256) {
        acc = fmaf(hf[j], attn_w[j], acc);
        acc = fmaf(hb[j], attn_w[HID + j], acc);
    }
    __shared__ float red[8];
    #pragma unroll
    for (int off = 16; off; off >>= 1)
        acc += __shfl_down_sync(0xffffffffu, acc, off);
    if ((tid & 31) == 0) red[tid >> 5] = acc;
    __syncthreads();
    if (tid == 0) {
        float s = 0.0f;
        #pragma unroll
        for (int i = 0; i < 8; i++) s += red[i];
        g_scores[t] = s + attn_b[0];
    }
}

// ---------------- kernel 4: entity span softmax + weighted pooling -----------
__global__ void __launch_bounds__(256) entity_kernel(
    const int* __restrict__ eidx, float* __restrict__ out)
{
    const int e = blockIdx.x;
    __shared__ float wsh[NL];
    __shared__ int   ish[NL];
    const int tid = threadIdx.x;

    if (tid < 32) {
        int   idx = 0;
        float sc  = -1e30f;
        if (tid < NL) {
            int raw = eidx[e * NL + tid];
            if (raw >= 0) { idx = raw; sc = g_scores[raw]; }
            else          { idx = 0;   sc = -1e9f; }
        }
        float m = sc;
        #pragma unroll
        for (int off = 16; off; off >>= 1)
            m = fmaxf(m, __shfl_xor_sync(0xffffffffu, m, off));
        float ex = (tid < NL) ? __expf(sc - m) : 0.0f;
        float sum = ex;
        #pragma unroll
        for (int off = 16; off; off >>= 1)
            sum += __shfl_xor_sync(0xffffffffu, sum, off);
        if (tid < NL) { wsh[tid] = ex / sum; ish[tid] = idx; }
    }
    __syncthreads();

    for (int d = tid; d < 2 * HID; d += 256) {
        float acc = 0.0f;
        #pragma unroll
        for (int l = 0; l < NL; l++) {
            int t = ish[l];
            float v = (d < HID) ? g_hs[0][t][d] : g_hs[1][t][d - HID];
            acc = fmaf(wsh[l], v, acc);
        }
        out[(long)e * (2 * HID) + d] = acc;
    }
}

// ---------------- launch ------------------------------------------------------
extern "C" void kernel_launch(void* const* d_in, const int* in_sizes, int n_in,
                              void* d_out, int out_size)
{
    const int*   sent   = (const int*)  d_in[0];
    const int*   eidx   = (const int*)  d_in[1];
    const float* emb    = (const float*)d_in[2];
    const float* Wi_f   = (const float*)d_in[3];
    const float* Wh_f   = (const float*)d_in[4];
    const float* b_f    = (const float*)d_in[5];
    const float* Wi_b   = (const float*)d_in[6];
    const float* Wh_b   = (const float*)d_in[7];
    const float* b_b    = (const float*)d_in[8];
    const float* attn_w = (const float*)d_in[9];
    const float* attn_b = (const float*)d_in[10];
    float* out = (float*)d_out;

    dim3 gg(H4 / 64, SLEN / 64, 2);
    xw_gemm_kernel<<<gg, 256>>>(sent, emb, Wi_f, b_f, Wi_b, b_b);
    lstm_kernel<<<2 * GCTA, 512>>>(Wh_f, Wh_b);
    scores_kernel<<<SLEN, 256>>>(attn_w, attn_b);
    entity_kernel<<<NE, 256>>>(eidx, out);
}

// round 3
// speedup vs baseline: 1.0987x; 1.0987x over previous
#include <cuda_runtime.h>
#include <math.h>

#define SLEN 4096
#define DIM  256
#define HID  512
#define H4   2048
#define NE   2000
#define NL   20
#define GCTA 32      // CTAs per direction
#define HPC  16      // h-indices per CTA (HID / GCTA)

// ---------------- device scratch (static: no runtime allocation) -------------
__device__ float g_xw[2][SLEN][H4];          // 64 MB: precomputed x@Wi^T + b
__device__ float g_hs[2][SLEN][HID];         // 16 MB: full hidden-state history
__device__ float g_scores[SLEN];
__device__ unsigned long long g_ctr[2][32];  // one arrival counter per direction (padded)

__device__ __forceinline__ float tanh_fast(float x) {
    float r;
    asm("tanh.approx.f32 %0, %1;" : "=f"(r) : "f"(x));
    return r;
}
__device__ __forceinline__ float sigmoid_fast(float x) {
    return fmaf(tanh_fast(0.5f * x), 0.5f, 0.5f);
}

// 16-byte .cg load returning two packed u64 (f32x2 pairs)
__device__ __forceinline__ void ldcg_v2u64(const void* p,
                                           unsigned long long& a,
                                           unsigned long long& b) {
    asm volatile("ld.global.cg.v2.u64 {%0,%1}, [%2];"
                 : "=l"(a), "=l"(b) : "l"(p) : "memory");
}

// ---------------- kernel 1: xW GEMM with fused embedding gather --------------
// C[m][n] = sum_k emb[sent[m]][k] * Wi[n][k] + b[n];  M=4096, N=2048, K=256
__global__ void __launch_bounds__(256) xw_gemm_kernel(
    const int* __restrict__ sent, const float* __restrict__ emb,
    const float* __restrict__ Wi_f, const float* __restrict__ b_f,
    const float* __restrict__ Wi_b, const float* __restrict__ b_b)
{
    // reset LSTM arrival counters (stream-ordered before lstm_kernel)
    if (blockIdx.x == 0 && blockIdx.y == 0 && blockIdx.z == 0 && threadIdx.x == 0) {
        g_ctr[0][0] = 0ull;
        g_ctr[1][0] = 0ull;
    }

    const int dir = blockIdx.z;
    const float* __restrict__ Wi   = dir ? Wi_b : Wi_f;
    const float* __restrict__ bias = dir ? b_b : b_f;
    const int n0 = blockIdx.x * 64;
    const int m0 = blockIdx.y * 64;

    __shared__ float As[16][64];
    __shared__ float Bs[16][64];
    __shared__ int   rows[64];

    const int tid = threadIdx.x;
    if (tid < 64) rows[tid] = sent[m0 + tid];
    __syncthreads();

    const int lm = tid >> 2;          // 0..63 (row within tile)
    const int lk = (tid & 3) * 4;     // 0,4,8,12 (k offset)
    const int ty = (tid >> 4) * 4;    // m micro-offset
    const int tx = (tid & 15) * 4;    // n micro-offset

    float acc[4][4];
    #pragma unroll
    for (int i = 0; i < 4; i++)
        #pragma unroll
        for (int j = 0; j < 4; j++) acc[i][j] = 0.0f;

    for (int k0 = 0; k0 < DIM; k0 += 16) {
        float4 a = *(const float4*)&emb[(long)rows[lm] * DIM + k0 + lk];
        float4 b = *(const float4*)&Wi[(long)(n0 + lm) * DIM + k0 + lk];
        __syncthreads();
        As[lk + 0][lm] = a.x; As[lk + 1][lm] = a.y;
        As[lk + 2][lm] = a.z; As[lk + 3][lm] = a.w;
        Bs[lk + 0][lm] = b.x; Bs[lk + 1][lm] = b.y;
        Bs[lk + 2][lm] = b.z; Bs[lk + 3][lm] = b.w;
        __syncthreads();
        #pragma unroll
        for (int kk = 0; kk < 16; kk++) {
            float4 a4 = *(const float4*)&As[kk][ty];
            float4 b4 = *(const float4*)&Bs[kk][tx];
            float av[4] = {a4.x, a4.y, a4.z, a4.w};
            float bv[4] = {b4.x, b4.y, b4.z, b4.w};
            #pragma unroll
            for (int i = 0; i < 4; i++)
                #pragma unroll
                for (int j = 0; j < 4; j++)
                    acc[i][j] = fmaf(av[i], bv[j], acc[i][j]);
        }
    }

    float4 bb = *(const float4*)&bias[n0 + tx];
    float bvv[4] = {bb.x, bb.y, bb.z, bb.w};
    #pragma unroll
    for (int i = 0; i < 4; i++) {
        float4 o;
        o.x = acc[i][0] + bvv[0];
        o.y = acc[i][1] + bvv[1];
        o.z = acc[i][2] + bvv[2];
        o.w = acc[i][3] + bvv[3];
        *(float4*)&g_xw[dir][m0 + ty + i][n0 + tx] = o;
    }
}

// ---------------- kernel 2: persistent BiLSTM, release/acquire counter sync --
__global__ void __launch_bounds__(512, 1) lstm_kernel(
    const float* __restrict__ Wh_f, const float* __restrict__ Wh_b)
{
    const int dir  = (blockIdx.x >= GCTA) ? 1 : 0;
    const int g    = blockIdx.x & (GCTA - 1);
    const float* __restrict__ Wh = dir ? Wh_b : Wh_f;

    const int tid  = threadIdx.x;
    const int w    = tid >> 5;       // warp -> local h-index
    const int lane = tid & 31;
    const int hidx = g * HPC + w;    // global h-index 0..511
    const int k0   = lane * 16;      // k slice (16 floats = 8 packed f32x2)

    // recurrent weights, packed as f32x2 pairs along k (natural layout)
    unsigned long long wi2[8], wf2[8], wg2[8], wo2[8];
    {
        const char* pi = (const char*)&Wh[(long)(0 * HID + hidx) * HID + k0];
        const char* pf = (const char*)&Wh[(long)(1 * HID + hidx) * HID + k0];
        const char* pg = (const char*)&Wh[(long)(2 * HID + hidx) * HID + k0];
        const char* po = (const char*)&Wh[(long)(3 * HID + hidx) * HID + k0];
        #pragma unroll
        for (int q = 0; q < 4; q++) {
            ldcg_v2u64(pi + 16 * q, wi2[2*q], wi2[2*q+1]);
            ldcg_v2u64(pf + 16 * q, wf2[2*q], wf2[2*q+1]);
            ldcg_v2u64(pg + 16 * q, wg2[2*q], wg2[2*q+1]);
            ldcg_v2u64(po + 16 * q, wo2[2*q], wo2[2*q+1]);
        }
    }

    unsigned long long* ctr = &g_ctr[dir][0];

    float c = 0.0f;   // cell state (lane 0 of each warp owns it)
    float* hs = &g_hs[dir][0][0];
    const float* xw = &g_xw[dir][0][0];

    for (int s = 0; s < SLEN; s++) {
        const int tok = dir ? (SLEN - 1 - s) : s;

        // prefetch input projection (independent of h) before polling
        float xi = 0.f, xf = 0.f, xg = 0.f, xo = 0.f;
        if (lane == 0) {
            const float* xr = xw + (long)tok * H4 + hidx;
            xi = __ldcg(xr);
            xf = __ldcg(xr + HID);
            xg = __ldcg(xr + 2 * HID);
            xo = __ldcg(xr + 3 * HID);
        }

        if (s > 0) {
            if (tid == 0) {
                const unsigned long long tgt = 32ull * (unsigned long long)s;
                unsigned long long v;
                do {
                    asm volatile("ld.acquire.gpu.global.u64 %0, [%1];"
                                 : "=l"(v) : "l"(ctr) : "memory");
                } while (v < tgt);
            }
            __syncthreads();
        }

        unsigned long long zi2 = 0ull, zf2 = 0ull, zg2 = 0ull, zo2 = 0ull;
        if (s > 0) {
            const int ptok = dir ? (tok + 1) : (tok - 1);
            const char* hp = (const char*)(hs + (long)ptok * HID + k0);
            unsigned long long hv[8];
            ldcg_v2u64(hp +  0, hv[0], hv[1]);
            ldcg_v2u64(hp + 16, hv[2], hv[3]);
            ldcg_v2u64(hp + 32, hv[4], hv[5]);
            ldcg_v2u64(hp + 48, hv[6], hv[7]);
            #pragma unroll
            for (int j = 0; j < 8; j++) {
                asm("fma.rn.f32x2 %0, %1, %2, %0;" : "+l"(zi2) : "l"(wi2[j]), "l"(hv[j]));
                asm("fma.rn.f32x2 %0, %1, %2, %0;" : "+l"(zf2) : "l"(wf2[j]), "l"(hv[j]));
                asm("fma.rn.f32x2 %0, %1, %2, %0;" : "+l"(zg2) : "l"(wg2[j]), "l"(hv[j]));
                asm("fma.rn.f32x2 %0, %1, %2, %0;" : "+l"(zo2) : "l"(wo2[j]), "l"(hv[j]));
            }
        }

        // unpack + warp reduction over the 32 k-slices
        float zi, zf, zg, zo;
        {
            float a, b;
            asm("mov.b64 {%0,%1}, %2;" : "=f"(a), "=f"(b) : "l"(zi2)); zi = a + b;
            asm("mov.b64 {%0,%1}, %2;" : "=f"(a), "=f"(b) : "l"(zf2)); zf = a + b;
            asm("mov.b64 {%0,%1}, %2;" : "=f"(a), "=f"(b) : "l"(zg2)); zg = a + b;
            asm("mov.b64 {%0,%1}, %2;" : "=f"(a), "=f"(b) : "l"(zo2)); zo = a + b;
        }
        #pragma unroll
        for (int off = 16; off; off >>= 1) {
            zi += __shfl_down_sync(0xffffffffu, zi, off);
            zf += __shfl_down_sync(0xffffffffu, zf, off);
            zg += __shfl_down_sync(0xffffffffu, zg, off);
            zo += __shfl_down_sync(0xffffffffu, zo, off);
        }

        if (lane == 0) {
            zi += xi; zf += xf; zg += xg; zo += xo;
            float i_ = sigmoid_fast(zi);
            float f_ = sigmoid_fast(zf);
            float o_ = sigmoid_fast(zo);
            float gg = tanh_fast(zg);
            c = fmaf(f_, c, i_ * gg);
            float h = o_ * tanh_fast(c);
            __stcg(hs + (long)tok * HID + hidx, h);
        }
        __syncthreads();   // all warps' h stores happen-before the release below
        if (tid == 0) {
            asm volatile("red.release.gpu.global.add.u64 [%0], %1;"
                         :: "l"(ctr), "l"(1ull) : "memory");
        }
    }
}

// ---------------- kernel 3: attention scores ---------------------------------
__global__ void __launch_bounds__(256) scores_kernel(
    const float* __restrict__ attn_w, const float* __restrict__ attn_b)
{
    const int t = blockIdx.x;
    const int tid = threadIdx.x;
    float acc = 0.0f;
    const float* hf = &g_hs[0][t][0];
    const float* hb = &g_hs[1][t][0];
    for (int j = tid; j < HID; j += 256) {
        acc = fmaf(hf[j], attn_w[j], acc);
        acc = fmaf(hb[j], attn_w[HID + j], acc);
    }
    __shared__ float red[8];
    #pragma unroll
    for (int off = 16; off; off >>= 1)
        acc += __shfl_down_sync(0xffffffffu, acc, off);
    if ((tid & 31) == 0) red[tid >> 5] = acc;
    __syncthreads();
    if (tid == 0) {
        float s = 0.0f;
        #pragma unroll
        for (int i = 0; i < 8; i++) s += red[i];
        g_scores[t] = s + attn_b[0];
    }
}

// ---------------- kernel 4: entity span softmax + weighted pooling -----------
__global__ void __launch_bounds__(256) entity_kernel(
    const int* __restrict__ eidx, float* __restrict__ out)
{
    const int e = blockIdx.x;
    __shared__ float wsh[NL];
    __shared__ int   ish[NL];
    const int tid = threadIdx.x;

    if (tid < 32) {
        int   idx = 0;
        float sc  = -1e30f;
        if (tid < NL) {
            int raw = eidx[e * NL + tid];
            if (raw >= 0) { idx = raw; sc = g_scores[raw]; }
            else          { idx = 0;   sc = -1e9f; }
        }
        float m = sc;
        #pragma unroll
        for (int off = 16; off; off >>= 1)
            m = fmaxf(m, __shfl_xor_sync(0xffffffffu, m, off));
        float ex = (tid < NL) ? __expf(sc - m) : 0.0f;
        float sum = ex;
        #pragma unroll
        for (int off = 16; off; off >>= 1)
            sum += __shfl_xor_sync(0xffffffffu, sum, off);
        if (tid < NL) { wsh[tid] = ex / sum; ish[tid] = idx; }
    }
    __syncthreads();

    for (int d = tid; d < 2 * HID; d += 256) {
        float acc = 0.0f;
        #pragma unroll
        for (int l = 0; l < NL; l++) {
            int t = ish[l];
            float v = (d < HID) ? g_hs[0][t][d] : g_hs[1][t][d - HID];
            acc = fmaf(wsh[l], v, acc);
        }
        out[(long)e * (2 * HID) + d] = acc;
    }
}

// ---------------- launch ------------------------------------------------------
extern "C" void kernel_launch(void* const* d_in, const int* in_sizes, int n_in,
                              void* d_out, int out_size)
{
    const int*   sent   = (const int*)  d_in[0];
    const int*   eidx   = (const int*)  d_in[1];
    const float* emb    = (const float*)d_in[2];
    const float* Wi_f   = (const float*)d_in[3];
    const float* Wh_f   = (const float*)d_in[4];
    const float* b_f    = (const float*)d_in[5];
    const float* Wi_b   = (const float*)d_in[6];
    const float* Wh_b   = (const float*)d_in[7];
    const float* b_b    = (const float*)d_in[8];
    const float* attn_w = (const float*)d_in[9];
    const float* attn_b = (const float*)d_in[10];
    float* out = (float*)d_out;

    dim3 gg(H4 / 64, SLEN / 64, 2);
    xw_gemm_kernel<<<gg, 256>>>(sent, emb, Wi_f, b_f, Wi_b, b_b);
    lstm_kernel<<<2 * GCTA, 512>>>(Wh_f, Wh_b);
    scores_kernel<<<SLEN, 256>>>(attn_w, attn_b);
    entity_kernel<<<NE, 256>>>(eidx, out);
}

// round 5
// speedup vs baseline: 3.0918x; 2.8139x over previous
#include <cuda_runtime.h>
#include <math.h>

#define SLEN 4096
#define DIM  256
#define HID  512
#define H4   2048
#define NE   2000
#define NL   20
#define GCTA 64      // CTAs per direction
#define HPC  8       // h-indices per CTA (HID / GCTA)
#define LTHR 256     // threads per LSTM CTA (8 warps)

// ---------------- device scratch (static: no runtime allocation) -------------
__device__ float g_xw[2][SLEN][H4];                     // 64 MB: x@Wi^T + b
__device__ float g_hs[2][SLEN][HID];                    // 16 MB: plain h history (epilogue)
__device__ unsigned long long g_hpub[2][SLEN][HID];     // 32 MB: {tag:u32 | h:f32} publication
__device__ float g_scores[SLEN];

#define NPUB (2 * SLEN * HID)   // u64 words in g_hpub

__device__ __forceinline__ float tanh_fast(float x) {
    float r;
    asm("tanh.approx.f32 %0, %1;" : "=f"(r) : "f"(x));
    return r;
}
__device__ __forceinline__ float sigmoid_fast(float x) {
    return fmaf(tanh_fast(0.5f * x), 0.5f, 0.5f);
}

// 16-byte .cg load returning two packed u64 (f32x2 pairs)
__device__ __forceinline__ void ldcg_v2u64(const void* p,
                                           unsigned long long& a,
                                           unsigned long long& b) {
    asm volatile("ld.global.cg.v2.u64 {%0,%1}, [%2];"
                 : "=l"(a), "=l"(b) : "l"(p) : "memory");
}

__device__ __forceinline__ unsigned long long ld_relaxed_u64(const unsigned long long* p) {
    unsigned long long v;
    asm volatile("ld.relaxed.gpu.global.u64 %0, [%1];" : "=l"(v) : "l"(p) : "memory");
    return v;
}
__device__ __forceinline__ void st_relaxed_u64(unsigned long long* p, unsigned long long v) {
    asm volatile("st.relaxed.gpu.global.u64 [%0], %1;" :: "l"(p), "l"(v) : "memory");
}

// padded smem index: +2 words every 16 -> stride 18, 8B-aligned, <=2-way conflicts
__device__ __forceinline__ int pidx(int i) { return i + ((i >> 4) << 1); }

// ---------------- kernel 1: xW GEMM + g_hpub tag reset -----------------------
// C[m][n] = sum_k emb[sent[m]][k] * Wi[n][k] + b[n];  M=4096, N=2048, K=256
__global__ void __launch_bounds__(256) xw_gemm_kernel(
    const int* __restrict__ sent, const float* __restrict__ emb,
    const float* __restrict__ Wi_f, const float* __restrict__ b_f,
    const float* __restrict__ Wi_b, const float* __restrict__ b_b)
{
    // zero the publication buffer: every run starts with virgin tags.
    {
        const int nblk = gridDim.x * gridDim.y * gridDim.z;   // 4096
        const int bid  = blockIdx.x + gridDim.x * (blockIdx.y + gridDim.y * blockIdx.z);
        unsigned long long* pub = &g_hpub[0][0][0];
        const int total = nblk * 256;                          // 1,048,576 threads
        for (int i = bid * 256 + threadIdx.x; i < NPUB; i += total)
            pub[i] = 0ull;
    }

    const int dir = blockIdx.z;
    const float* __restrict__ Wi   = dir ? Wi_b : Wi_f;
    const float* __restrict__ bias = dir ? b_b : b_f;
    const int n0 = blockIdx.x * 64;
    const int m0 = blockIdx.y * 64;

    __shared__ float As[16][64];
    __shared__ float Bs[16][64];
    __shared__ int   rows[64];

    const int tid = threadIdx.x;
    if (tid < 64) rows[tid] = sent[m0 + tid];
    __syncthreads();

    const int lm = tid >> 2;
    const int lk = (tid & 3) * 4;
    const int ty = (tid >> 4) * 4;
    const int tx = (tid & 15) * 4;

    float acc[4][4];
    #pragma unroll
    for (int i = 0; i < 4; i++)
        #pragma unroll
        for (int j = 0; j < 4; j++) acc[i][j] = 0.0f;

    for (int k0 = 0; k0 < DIM; k0 += 16) {
        float4 a = *(const float4*)&emb[(long)rows[lm] * DIM + k0 + lk];
        float4 b = *(const float4*)&Wi[(long)(n0 + lm) * DIM + k0 + lk];
        __syncthreads();
        As[lk + 0][lm] = a.x; As[lk + 1][lm] = a.y;
        As[lk + 2][lm] = a.z; As[lk + 3][lm] = a.w;
        Bs[lk + 0][lm] = b.x; Bs[lk + 1][lm] = b.y;
        Bs[lk + 2][lm] = b.z; Bs[lk + 3][lm] = b.w;
        __syncthreads();
        #pragma unroll
        for (int kk = 0; kk < 16; kk++) {
            float4 a4 = *(const float4*)&As[kk][ty];
            float4 b4 = *(const float4*)&Bs[kk][tx];
            float av[4] = {a4.x, a4.y, a4.z, a4.w};
            float bv[4] = {b4.x, b4.y, b4.z, b4.w};
            #pragma unroll
            for (int i = 0; i < 4; i++)
                #pragma unroll
                for (int j = 0; j < 4; j++)
                    acc[i][j] = fmaf(av[i], bv[j], acc[i][j]);
        }
    }

    float4 bb = *(const float4*)&bias[n0 + tx];
    float bvv[4] = {bb.x, bb.y, bb.z, bb.w};
    #pragma unroll
    for (int i = 0; i < 4; i++) {
        float4 o;
        o.x = acc[i][0] + bvv[0];
        o.y = acc[i][1] + bvv[1];
        o.z = acc[i][2] + bvv[2];
        o.w = acc[i][3] + bvv[3];
        *(float4*)&g_xw[dir][m0 + ty + i][n0 + tx] = o;
    }
}

// ---------------- kernel 2: persistent BiLSTM, tag-in-data sync --------------
__global__ void __launch_bounds__(LTHR) lstm_kernel(
    const float* __restrict__ Wh_f, const float* __restrict__ Wh_b)
{
    __shared__ __align__(16) float sm_h[2][576];   // ping-pong, stride-18 padded

    const int dir  = (blockIdx.x >= GCTA) ? 1 : 0;
    const int g    = blockIdx.x & (GCTA - 1);
    const float* __restrict__ Wh = dir ? Wh_b : Wh_f;

    const int tid  = threadIdx.x;        // 0..255
    const int w    = tid >> 5;           // warp -> local h-index (0..7)
    const int lane = tid & 31;
    const int hidx = g * HPC + w;        // global h-index 0..511
    const int k0   = lane * 16;          // k slice (16 floats = 8 packed f32x2)

    // recurrent weights, packed as f32x2 pairs along k
    unsigned long long wi2[8], wf2[8], wg2[8], wo2[8];
    {
        const char* pi = (const char*)&Wh[(long)(0 * HID + hidx) * HID + k0];
        const char* pf = (const char*)&Wh[(long)(1 * HID + hidx) * HID + k0];
        const char* pg = (const char*)&Wh[(long)(2 * HID + hidx) * HID + k0];
        const char* po = (const char*)&Wh[(long)(3 * HID + hidx) * HID + k0];
        #pragma unroll
        for (int q = 0; q < 4; q++) {
            ldcg_v2u64(pi + 16 * q, wi2[2*q], wi2[2*q+1]);
            ldcg_v2u64(pf + 16 * q, wf2[2*q], wf2[2*q+1]);
            ldcg_v2u64(pg + 16 * q, wg2[2*q], wg2[2*q+1]);
            ldcg_v2u64(po + 16 * q, wo2[2*q], wo2[2*q+1]);
        }
    }

    float c = 0.0f;   // cell state (lane 0 of each warp owns it)
    const float* xw = &g_xw[dir][0][0];

    // 1-step-ahead double-buffered input projection (lane 0 only)
    float xci = 0.f, xcf = 0.f, xcg = 0.f, xco = 0.f;
    if (lane == 0) {
        const int t0 = dir ? (SLEN - 1) : 0;
        const float* xr = xw + (long)t0 * H4 + hidx;
        xci = __ldcg(xr);
        xcf = __ldcg(xr + HID);
        xcg = __ldcg(xr + 2 * HID);
        xco = __ldcg(xr + 3 * HID);
    }

    for (int s = 0; s < SLEN; s++) {
        const int tok = dir ? (SLEN - 1 - s) : s;

        // issue next step's xW loads immediately (hidden behind poll + matvec)
        float xni = 0.f, xnf = 0.f, xng = 0.f, xno = 0.f;
        if (lane == 0) {
            int tn = dir ? (tok - 1) : (tok + 1);
            tn = tn < 0 ? 0 : (tn > SLEN - 1 ? SLEN - 1 : tn);
            const float* xr = xw + (long)tn * H4 + hidx;
            xni = __ldcg(xr);
            xnf = __ldcg(xr + HID);
            xng = __ldcg(xr + 2 * HID);
            xno = __ldcg(xr + 3 * HID);
        }

        const int p = s & 1;

        // poll previous step's h: each thread owns 2 of the 512 words
        if (s > 0) {
            const int ptok = dir ? (tok + 1) : (tok - 1);
            const unsigned long long* pp = &g_hpub[dir][ptok][2 * tid];
            unsigned long long v0, v1;
            do { v0 = ld_relaxed_u64(pp);     } while ((unsigned)(v0 >> 32) != (unsigned)s);
            do { v1 = ld_relaxed_u64(pp + 1); } while ((unsigned)(v1 >> 32) != (unsigned)s);
            float2 hh = make_float2(__uint_as_float((unsigned)v0),
                                    __uint_as_float((unsigned)v1));
            *(float2*)&sm_h[p][pidx(2 * tid)] = hh;
        }
        __syncthreads();

        unsigned long long zi2 = 0ull, zf2 = 0ull, zg2 = 0ull, zo2 = 0ull;
        if (s > 0) {
            const unsigned long long* hb =
                (const unsigned long long*)&sm_h[p][18 * lane];
            #pragma unroll
            for (int j = 0; j < 8; j++) {
                const unsigned long long hv = hb[j];
                asm("fma.rn.f32x2 %0, %1, %2, %0;" : "+l"(zi2) : "l"(wi2[j]), "l"(hv));
                asm("fma.rn.f32x2 %0, %1, %2, %0;" : "+l"(zf2) : "l"(wf2[j]), "l"(hv));
                asm("fma.rn.f32x2 %0, %1, %2, %0;" : "+l"(zg2) : "l"(wg2[j]), "l"(hv));
                asm("fma.rn.f32x2 %0, %1, %2, %0;" : "+l"(zo2) : "l"(wo2[j]), "l"(hv));
            }
        }

        // unpack + warp reduction over the 32 k-slices
        float zi, zf, zg, zo;
        {
            float a, b;
            asm("mov.b64 {%0,%1}, %2;" : "=f"(a), "=f"(b) : "l"(zi2)); zi = a + b;
            asm("mov.b64 {%0,%1}, %2;" : "=f"(a), "=f"(b) : "l"(zf2)); zf = a + b;
            asm("mov.b64 {%0,%1}, %2;" : "=f"(a), "=f"(b) : "l"(zg2)); zg = a + b;
            asm("mov.b64 {%0,%1}, %2;" : "=f"(a), "=f"(b) : "l"(zo2)); zo = a + b;
        }
        #pragma unroll
        for (int off = 16; off; off >>= 1) {
            zi += __shfl_down_sync(0xffffffffu, zi, off);
            zf += __shfl_down_sync(0xffffffffu, zf, off);
            zg += __shfl_down_sync(0xffffffffu, zg, off);
            zo += __shfl_down_sync(0xffffffffu, zo, off);
        }

        if (lane == 0) {
            zi += xci; zf += xcf; zg += xcg; zo += xco;
            float i_ = sigmoid_fast(zi);
            float f_ = sigmoid_fast(zf);
            float o_ = sigmoid_fast(zo);
            float gg = tanh_fast(zg);
            c = fmaf(f_, c, i_ * gg);
            float h = o_ * tanh_fast(c);

            g_hs[dir][tok][hidx] = h;             // plain copy for epilogue
            unsigned long long pub =
                ((unsigned long long)(unsigned)(s + 1) << 32) |
                (unsigned long long)__float_as_uint(h);
            st_relaxed_u64(&g_hpub[dir][tok][hidx], pub);
        }

        xci = xni; xcf = xnf; xcg = xng; xco = xno;
    }
}

// ---------------- kernel 3: attention scores ---------------------------------
__global__ void __launch_bounds__(256) scores_kernel(
    const float* __restrict__ attn_w, const float* __restrict__ attn_b)
{
    const int t = blockIdx.x;
    const int tid = threadIdx.x;
    float acc = 0.0f;
    const float* hf = &g_hs[0][t][0];
    const float* hb = &g_hs[1][t][0];
    for (int j = tid; j < HID; j += 256) {
        acc = fmaf(hf[j], attn_w[j], acc);
        acc = fmaf(hb[j], attn_w[HID + j], acc);
    }
    __shared__ float red[8];
    #pragma unroll
    for (int off = 16; off; off >>= 1)
        acc += __shfl_down_sync(0xffffffffu, acc, off);
    if ((tid & 31) == 0) red[tid >> 5] = acc;
    __syncthreads();
    if (tid == 0) {
        float s = 0.0f;
        #pragma unroll
        for (int i = 0; i < 8; i++) s += red[i];
        g_scores[t] = s + attn_b[0];
    }
}

// ---------------- kernel 4: entity span softmax + weighted pooling -----------
__global__ void __launch_bounds__(256) entity_kernel(
    const int* __restrict__ eidx, float* __restrict__ out)
{
    const int e = blockIdx.x;
    __shared__ float wsh[NL];
    __shared__ int   ish[NL];
    const int tid = threadIdx.x;

    if (tid < 32) {
        int   idx = 0;
        float sc  = -1e30f;
        if (tid < NL) {
            int raw = eidx[e * NL + tid];
            if (raw >= 0) { idx = raw; sc = g_scores[raw]; }
            else          { idx = 0;   sc = -1e9f; }
        }
        float m = sc;
        #pragma unroll
        for (int off = 16; off; off >>= 1)
            m = fmaxf(m, __shfl_xor_sync(0xffffffffu, m, off));
        float ex = (tid < NL) ? __expf(sc - m) : 0.0f;
        float sum = ex;
        #pragma unroll
        for (int off = 16; off; off >>= 1)
            sum += __shfl_xor_sync(0xffffffffu, sum, off);
        if (tid < NL) { wsh[tid] = ex / sum; ish[tid] = idx; }
    }
    __syncthreads();

    for (int d = tid; d < 2 * HID; d += 256) {
        float acc = 0.0f;
        #pragma unroll
        for (int l = 0; l < NL; l++) {
            int t = ish[l];
            float v = (d < HID) ? g_hs[0][t][d] : g_hs[1][t][d - HID];
            acc = fmaf(wsh[l], v, acc);
        }
        out[(long)e * (2 * HID) + d] = acc;
    }
}

// ---------------- launch ------------------------------------------------------
extern "C" void kernel_launch(void* const* d_in, const int* in_sizes, int n_in,
                              void* d_out, int out_size)
{
    const int*   sent   = (const int*)  d_in[0];
    const int*   eidx   = (const int*)  d_in[1];
    const float* emb    = (const float*)d_in[2];
    const float* Wi_f   = (const float*)d_in[3];
    const float* Wh_f   = (const float*)d_in[4];
    const float* b_f    = (const float*)d_in[5];
    const float* Wi_b   = (const float*)d_in[6];
    const float* Wh_b   = (const float*)d_in[7];
    const float* b_b    = (const float*)d_in[8];
    const float* attn_w = (const float*)d_in[9];
    const float* attn_b = (const float*)d_in[10];
    float* out = (float*)d_out;

    dim3 gg(H4 / 64, SLEN / 64, 2);
    xw_gemm_kernel<<<gg, 256>>>(sent, emb, Wi_f, b_f, Wi_b, b_b);
    lstm_kernel<<<2 * GCTA, LTHR>>>(Wh_f, Wh_b);
    scores_kernel<<<SLEN, 256>>>(attn_w, attn_b);
    entity_kernel<<<NE, 256>>>(eidx, out);
}

// round 7
// speedup vs baseline: 3.2124x; 1.0390x over previous
#include <cuda_runtime.h>
#include <math.h>

#define SLEN 4096
#define DIM  256
#define HID  512
#define H4   2048
#define NE   2000
#define NL   20
#define GCTA 64      // CTAs per direction
#define HPC  8       // h-indices per CTA (HID / GCTA)
#define LTHR 256     // threads per LSTM CTA (8 warps)

// ---------------- device scratch (static: no runtime allocation) -------------
__device__ float g_xw[2][SLEN][H4];                     // 64 MB: x@Wi^T + b
__device__ unsigned long long g_hpub[2][SLEN][HID];     // 32 MB: {tag:u32 | h:f32}
__device__ float g_scores[SLEN];

#define NPUB (2 * SLEN * HID)   // u64 words in g_hpub

__device__ __forceinline__ float tanh_fast(float x) {
    float r;
    asm("tanh.approx.f32 %0, %1;" : "=f"(r) : "f"(x));
    return r;
}
__device__ __forceinline__ float sigmoid_fast(float x) {
    return fmaf(tanh_fast(0.5f * x), 0.5f, 0.5f);
}

// 16-byte .cg load returning two packed u64 (f32x2 pairs) -- used for
// read-only data (weights), NOT for spin-polling.
__device__ __forceinline__ void ldcg_v2u64(const void* p,
                                           unsigned long long& a,
                                           unsigned long long& b) {
    asm volatile("ld.global.cg.v2.u64 {%0,%1}, [%2];"
                 : "=l"(a), "=l"(b) : "l"(p) : "memory");
}

// morally-strong relaxed atomics: guaranteed eventual visibility in spin loops
__device__ __forceinline__ unsigned long long ld_relaxed_u64(const unsigned long long* p) {
    unsigned long long v;
    asm volatile("ld.relaxed.gpu.global.u64 %0, [%1];" : "=l"(v) : "l"(p) : "memory");
    return v;
}
__device__ __forceinline__ void st_relaxed_u64(unsigned long long* p, unsigned long long v) {
    asm volatile("st.relaxed.gpu.global.u64 [%0], %1;" :: "l"(p), "l"(v) : "memory");
}

// padded smem index: +2 words every 16 -> stride 18, 8B-aligned, conflict-free LDS.64
__device__ __forceinline__ int pidx(int i) { return i + ((i >> 4) << 1); }

// ---------------- kernel 1: xW GEMM + g_hpub tag reset -----------------------
// C[m][n] = sum_k emb[sent[m]][k] * Wi[n][k] + b[n];  M=4096, N=2048, K=256
__global__ void __launch_bounds__(256) xw_gemm_kernel(
    const int* __restrict__ sent, const float* __restrict__ emb,
    const float* __restrict__ Wi_f, const float* __restrict__ b_f,
    const float* __restrict__ Wi_b, const float* __restrict__ b_b)
{
    // zero the publication buffer: every run starts with virgin tags.
    {
        const int nblk = gridDim.x * gridDim.y * gridDim.z;   // 4096
        const int bid  = blockIdx.x + gridDim.x * (blockIdx.y + gridDim.y * blockIdx.z);
        unsigned long long* pub = &g_hpub[0][0][0];
        const int total = nblk * 256;
        for (int i = bid * 256 + threadIdx.x; i < NPUB; i += total)
            pub[i] = 0ull;
    }

    const int dir = blockIdx.z;
    const float* __restrict__ Wi   = dir ? Wi_b : Wi_f;
    const float* __restrict__ bias = dir ? b_b : b_f;
    const int n0 = blockIdx.x * 64;
    const int m0 = blockIdx.y * 64;

    __shared__ float As[16][64];
    __shared__ float Bs[16][64];
    __shared__ int   rows[64];

    const int tid = threadIdx.x;
    if (tid < 64) rows[tid] = sent[m0 + tid];
    __syncthreads();

    const int lm = tid >> 2;
    const int lk = (tid & 3) * 4;
    const int ty = (tid >> 4) * 4;
    const int tx = (tid & 15) * 4;

    float acc[4][4];
    #pragma unroll
    for (int i = 0; i < 4; i++)
        #pragma unroll
        for (int j = 0; j < 4; j++) acc[i][j] = 0.0f;

    for (int k0 = 0; k0 < DIM; k0 += 16) {
        float4 a = *(const float4*)&emb[(long)rows[lm] * DIM + k0 + lk];
        float4 b = *(const float4*)&Wi[(long)(n0 + lm) * DIM + k0 + lk];
        __syncthreads();
        As[lk + 0][lm] = a.x; As[lk + 1][lm] = a.y;
        As[lk + 2][lm] = a.z; As[lk + 3][lm] = a.w;
        Bs[lk + 0][lm] = b.x; Bs[lk + 1][lm] = b.y;
        Bs[lk + 2][lm] = b.z; Bs[lk + 3][lm] = b.w;
        __syncthreads();
        #pragma unroll
        for (int kk = 0; kk < 16; kk++) {
            float4 a4 = *(const float4*)&As[kk][ty];
            float4 b4 = *(const float4*)&Bs[kk][tx];
            float av[4] = {a4.x, a4.y, a4.z, a4.w};
            float bv[4] = {b4.x, b4.y, b4.z, b4.w};
            #pragma unroll
            for (int i = 0; i < 4; i++)
                #pragma unroll
                for (int j = 0; j < 4; j++)
                    acc[i][j] = fmaf(av[i], bv[j], acc[i][j]);
        }
    }

    float4 bb = *(const float4*)&bias[n0 + tx];
    float bvv[4] = {bb.x, bb.y, bb.z, bb.w};
    #pragma unroll
    for (int i = 0; i < 4; i++) {
        float4 o;
        o.x = acc[i][0] + bvv[0];
        o.y = acc[i][1] + bvv[1];
        o.z = acc[i][2] + bvv[2];
        o.w = acc[i][3] + bvv[3];
        *(float4*)&g_xw[dir][m0 + ty + i][n0 + tx] = o;
    }
}

// ---------------- kernel 2: persistent BiLSTM, sweep-poll sync ----------------
__global__ void __launch_bounds__(LTHR) lstm_kernel(
    const float* __restrict__ Wh_f, const float* __restrict__ Wh_b)
{
    __shared__ __align__(16) float sm_h[2][576];   // ping-pong, stride-18 padded

    const int dir  = (blockIdx.x >= GCTA) ? 1 : 0;
    const int g    = blockIdx.x & (GCTA - 1);
    const float* __restrict__ Wh = dir ? Wh_b : Wh_f;

    const int tid  = threadIdx.x;        // 0..255
    const int w    = tid >> 5;           // warp -> local h-index (0..7)
    const int lane = tid & 31;
    const int hidx = g * HPC + w;        // global h-index 0..511
    const int k0   = lane * 16;          // k slice (16 floats = 8 packed f32x2)

    // recurrent weights, packed as f32x2 pairs along k
    unsigned long long wi2[8], wf2[8], wg2[8], wo2[8];
    {
        const char* pi = (const char*)&Wh[(long)(0 * HID + hidx) * HID + k0];
        const char* pf = (const char*)&Wh[(long)(1 * HID + hidx) * HID + k0];
        const char* pg = (const char*)&Wh[(long)(2 * HID + hidx) * HID + k0];
        const char* po = (const char*)&Wh[(long)(3 * HID + hidx) * HID + k0];
        #pragma unroll
        for (int q = 0; q < 4; q++) {
            ldcg_v2u64(pi + 16 * q, wi2[2*q], wi2[2*q+1]);
            ldcg_v2u64(pf + 16 * q, wf2[2*q], wf2[2*q+1]);
            ldcg_v2u64(pg + 16 * q, wg2[2*q], wg2[2*q+1]);
            ldcg_v2u64(po + 16 * q, wo2[2*q], wo2[2*q+1]);
        }
    }

    float c = 0.0f;   // cell state (lane 0 of each warp owns it)
    const float* xw = &g_xw[dir][0][0];

    // 1-step-ahead double-buffered input projection (lane 0 only)
    float xci = 0.f, xcf = 0.f, xcg = 0.f, xco = 0.f;
    if (lane == 0) {
        const int t0 = dir ? (SLEN - 1) : 0;
        const float* xr = xw + (long)t0 * H4 + hidx;
        xci = __ldcg(xr);
        xcf = __ldcg(xr + HID);
        xcg = __ldcg(xr + 2 * HID);
        xco = __ldcg(xr + 3 * HID);
    }

    for (int s = 0; s < SLEN; s++) {
        const int tok = dir ? (SLEN - 1 - s) : s;

        // issue next step's xW loads immediately (hidden behind poll + matvec)
        float xni = 0.f, xnf = 0.f, xng = 0.f, xno = 0.f;
        if (lane == 0) {
            int tn = dir ? (tok - 1) : (tok + 1);
            tn = tn < 0 ? 0 : (tn > SLEN - 1 ? SLEN - 1 : tn);
            const float* xr = xw + (long)tn * H4 + hidx;
            xni = __ldcg(xr);
            xnf = __ldcg(xr + HID);
            xng = __ldcg(xr + 2 * HID);
            xno = __ldcg(xr + 3 * HID);
        }

        const int p = s & 1;

        // ---- warp 0 sweep-polls ALL 512 previous-h words (relaxed, MLP=16) ----
        if (s > 0 && w == 0) {
            const int ptok = dir ? (tok + 1) : (tok - 1);
            const unsigned long long* base = &g_hpub[dir][ptok][0];
            const unsigned tagw = (unsigned)s;
            unsigned long long va[16];
            int bound = 10000;      // liveness fuse: proceed (wrong) instead of hanging
            unsigned ok;
            do {
                int good = 1;
                #pragma unroll
                for (int j = 0; j < 16; j++) {
                    va[j] = ld_relaxed_u64(base + j * 32 + lane);
                    good &= ((unsigned)(va[j] >> 32) == tagw);
                }
                ok = __all_sync(0xffffffffu, good);
            } while (!ok && --bound);
            #pragma unroll
            for (int j = 0; j < 16; j++)
                sm_h[p][pidx(j * 32 + lane)] = __uint_as_float((unsigned)va[j]);
        }
        __syncthreads();

        unsigned long long zi2 = 0ull, zf2 = 0ull, zg2 = 0ull, zo2 = 0ull;
        if (s > 0) {
            const unsigned long long* hb =
                (const unsigned long long*)&sm_h[p][18 * lane];
            #pragma unroll
            for (int j = 0; j < 8; j++) {
                const unsigned long long hv = hb[j];
                asm("fma.rn.f32x2 %0, %1, %2, %0;" : "+l"(zi2) : "l"(wi2[j]), "l"(hv));
                asm("fma.rn.f32x2 %0, %1, %2, %0;" : "+l"(zf2) : "l"(wf2[j]), "l"(hv));
                asm("fma.rn.f32x2 %0, %1, %2, %0;" : "+l"(zg2) : "l"(wg2[j]), "l"(hv));
                asm("fma.rn.f32x2 %0, %1, %2, %0;" : "+l"(zo2) : "l"(wo2[j]), "l"(hv));
            }
        }

        // unpack + warp reduction over the 32 k-slices
        float zi, zf, zg, zo;
        {
            float a, b;
            asm("mov.b64 {%0,%1}, %2;" : "=f"(a), "=f"(b) : "l"(zi2)); zi = a + b;
            asm("mov.b64 {%0,%1}, %2;" : "=f"(a), "=f"(b) : "l"(zf2)); zf = a + b;
            asm("mov.b64 {%0,%1}, %2;" : "=f"(a), "=f"(b) : "l"(zg2)); zg = a + b;
            asm("mov.b64 {%0,%1}, %2;" : "=f"(a), "=f"(b) : "l"(zo2)); zo = a + b;
        }
        #pragma unroll
        for (int off = 16; off; off >>= 1) {
            zi += __shfl_down_sync(0xffffffffu, zi, off);
            zf += __shfl_down_sync(0xffffffffu, zf, off);
            zg += __shfl_down_sync(0xffffffffu, zg, off);
            zo += __shfl_down_sync(0xffffffffu, zo, off);
        }

        if (lane == 0) {
            zi += xci; zf += xcf; zg += xcg; zo += xco;
            float i_ = sigmoid_fast(zi);
            float f_ = sigmoid_fast(zf);
            float o_ = sigmoid_fast(zo);
            float gg = tanh_fast(zg);
            c = fmaf(f_, c, i_ * gg);
            float h = o_ * tanh_fast(c);

            unsigned long long pub =
                ((unsigned long long)(unsigned)(s + 1) << 32) |
                (unsigned long long)__float_as_uint(h);
            st_relaxed_u64(&g_hpub[dir][tok][hidx], pub);
        }

        xci = xni; xcf = xnf; xcg = xng; xco = xno;
    }
}

// ---------------- kernel 3: attention scores ---------------------------------
__global__ void __launch_bounds__(256) scores_kernel(
    const float* __restrict__ attn_w, const float* __restrict__ attn_b)
{
    const int t = blockIdx.x;
    const int tid = threadIdx.x;
    float acc = 0.0f;
    const unsigned long long* hf = &g_hpub[0][t][0];
    const unsigned long long* hb = &g_hpub[1][t][0];
    for (int j = tid; j < HID; j += 256) {
        acc = fmaf(__uint_as_float((unsigned)hf[j]), attn_w[j], acc);
        acc = fmaf(__uint_as_float((unsigned)hb[j]), attn_w[HID + j], acc);
    }
    __shared__ float red[8];
    #pragma unroll
    for (int off = 16; off; off >>= 1)
        acc += __shfl_down_sync(0xffffffffu, acc, off);
    if ((tid & 31) == 0) red[tid >> 5] = acc;
    __syncthreads();
    if (tid == 0) {
        float s = 0.0f;
        #pragma unroll
        for (int i = 0; i < 8; i++) s += red[i];
        g_scores[t] = s + attn_b[0];
    }
}

// ---------------- kernel 4: entity span softmax + weighted pooling -----------
__global__ void __launch_bounds__(256) entity_kernel(
    const int* __restrict__ eidx, float* __restrict__ out)
{
    const int e = blockIdx.x;
    __shared__ float wsh[NL];
    __shared__ int   ish[NL];
    const int tid = threadIdx.x;

    if (tid < 32) {
        int   idx = 0;
        float sc  = -1e30f;
        if (tid < NL) {
            int raw = eidx[e * NL + tid];
            if (raw >= 0) { idx = raw; sc = g_scores[raw]; }
            else          { idx = 0;   sc = -1e9f; }
        }
        float m = sc;
        #pragma unroll
        for (int off = 16; off; off >>= 1)
            m = fmaxf(m, __shfl_xor_sync(0xffffffffu, m, off));
        float ex = (tid < NL) ? __expf(sc - m) : 0.0f;
        float sum = ex;
        #pragma unroll
        for (int off = 16; off; off >>= 1)
            sum += __shfl_xor_sync(0xffffffffu, sum, off);
        if (tid < NL) { wsh[tid] = ex / sum; ish[tid] = idx; }
    }
    __syncthreads();

    for (int d = tid; d < 2 * HID; d += 256) {
        float acc = 0.0f;
        #pragma unroll
        for (int l = 0; l < NL; l++) {
            int t = ish[l];
            unsigned long long v = (d < HID) ? g_hpub[0][t][d]
                                             : g_hpub[1][t][d - HID];
            acc = fmaf(wsh[l], __uint_as_float((unsigned)v), acc);
        }
        out[(long)e * (2 * HID) + d] = acc;
    }
}

// ---------------- launch ------------------------------------------------------
extern "C" void kernel_launch(void* const* d_in, const int* in_sizes, int n_in,
                              void* d_out, int out_size)
{
    const int*   sent   = (const int*)  d_in[0];
    const int*   eidx   = (const int*)  d_in[1];
    const float* emb    = (const float*)d_in[2];
    const float* Wi_f   = (const float*)d_in[3];
    const float* Wh_f   = (const float*)d_in[4];
    const float* b_f    = (const float*)d_in[5];
    const float* Wi_b   = (const float*)d_in[6];
    const float* Wh_b   = (const float*)d_in[7];
    const float* b_b    = (const float*)d_in[8];
    const float* attn_w = (const float*)d_in[9];
    const float* attn_b = (const float*)d_in[10];
    float* out = (float*)d_out;

    dim3 gg(H4 / 64, SLEN / 64, 2);
    xw_gemm_kernel<<<gg, 256>>>(sent, emb, Wi_f, b_f, Wi_b, b_b);
    lstm_kernel<<<2 * GCTA, LTHR>>>(Wh_f, Wh_b);
    scores_kernel<<<SLEN, 256>>>(attn_w, attn_b);
    entity_kernel<<<NE, 256>>>(eidx, out);
}